// round 16
// baseline (speedup 1.0000x reference)
#include <cuda_runtime.h>
#include <cuda_fp16.h>
#include <stdint.h>

// Problem constants
#define BATCH   512
#define IN_FLAT 1024
#define NEURONS 4096
#define FOCUS   64

// GEMM tiling (fp16 m16n8k16)
#define BM 128
#define BN 128
#define BK 128
#define TPB 128                    // 4 warps (2m x 2n), warp tile 64x64
#define KTILES (IN_FLAT / BK)      // 8

// Smem map (bytes)
#define OF_B0   98304              // A stages: 0, 32768, 65536 (3 x 32KB)
#define OF_PAIR 163840             // B buffers: 98304, 131072 (2 x 32KB)
#define OF_BIAS 196608             // pair table 32KB at 163840
#define SMEM_DYN 197120

// A operand, fragment-packed (uint4 chunks; device global, no allocation)
// chunk (kt16, m16, lane) = {a0,a1,a2,a3} of m16n8k16 -> 64*32*32 uint4 = 1 MB
__device__ uint4 g_xA[64 * 32 * 32];

// ---------------------------------------------------------------------------
__device__ __forceinline__ uint32_t smem_u32(const void* p) {
    uint32_t a;
    asm("{ .reg .u64 t; cvta.to.shared.u64 t, %1; cvt.u32.u64 %0, t; }" : "=r"(a) : "l"(p));
    return a;
}
__device__ __forceinline__ uint32_t pack_h2(float lo, float hi) {
    __half2 h = __floats2half2_rn(lo, hi);
    return *(uint32_t*)&h;
}
__device__ __forceinline__ void cp_async16(uint32_t sdst, const void* gsrc) {
    asm volatile("cp.async.cg.shared.global [%0], [%1], 16;"
                 :: "r"(sdst), "l"(__cvta_generic_to_global(gsrc)) : "memory");
}
__device__ __forceinline__ void mma_f16(float* c, const uint4& a,
                                        uint32_t b0, uint32_t b1) {
    asm volatile(
        "mma.sync.aligned.m16n8k16.row.col.f32.f16.f16.f32 "
        "{%0,%1,%2,%3}, {%4,%5,%6,%7}, {%8,%9}, {%0,%1,%2,%3};"
        : "+f"(c[0]), "+f"(c[1]), "+f"(c[2]), "+f"(c[3])
        : "r"(a.x), "r"(a.y), "r"(a.z), "r"(a.w), "r"(b0), "r"(b1));
}

// ---------------------------------------------------------------------------
// Kernel 1: convert x to A fragment chunks (one uint4 per thread).
__global__ void convert_x(const float* __restrict__ x) {
    int c = blockIdx.x * 128 + threadIdx.x;            // 0..65535
    int lane = c & 31, m16 = (c >> 5) & 31, kt16 = c >> 10;
    int g = lane >> 2, t = lane & 3;
    const float* r0 = x + (size_t)(m16 * 16 + g) * IN_FLAT;       // row g
    const float* r1 = r0 + 8 * IN_FLAT;                           // row g+8
    int k0 = kt16 * 16 + 2 * t;
    uint4 v;
    v.x = pack_h2(r0[k0],     r0[k0 + 1]);     // a0
    v.y = pack_h2(r1[k0],     r1[k0 + 1]);     // a1
    v.z = pack_h2(r0[k0 + 8], r0[k0 + 9]);     // a2
    v.w = pack_h2(r1[k0 + 8], r1[k0 + 9]);     // a3
    g_xA[c] = v;
}

// ---------------------------------------------------------------------------
// Kernel 2: GEMM with in-kernel B densification.
// Per kt, the NEXT B fragment tile is built in smem (zero + f16x2 scatter)
// interleaved into the HMMA stream's idle issue slots. No 8 MB W in gmem.
// ---------------------------------------------------------------------------
__global__ void __launch_bounds__(TPB, 1)
gemm_f16(const void*  __restrict__ conn_raw,
         const float* __restrict__ wgt,
         const float* __restrict__ bias,
         float* __restrict__ out) {
    extern __shared__ char smb[];
    const uint32_t sbase = smem_u32(smb);

    const int tid  = threadIdx.x;
    const int lane = tid & 31;
    const int wid  = tid >> 5;
    const int wm   = wid & 1;          // warp row -> m16 tiles {4wm..4wm+3}
    const int wn   = wid >> 1;         // warp col -> n16 tiles {4wn..4wn+3}
    const int n0   = blockIdx.x * BN;
    const int m0   = blockIdx.y * BM;
    const int mSlab = m0 >> 4;

    // ---- bias + pair table (idx<<16 | fp16 w) + zero both B buffers
    *(float*)(smb + OF_BIAS + tid * 4) = bias[n0 + tid];
    {
        const int* c32p = (const int*)conn_raw;
        bool is64 = true;                      // int64 sniff (values < 1024)
        #pragma unroll
        for (int k = 1; k < 64; k += 2) is64 &= (c32p[k] == 0);
        const long long* c64p = (const long long*)conn_raw;

        uint32_t* pr = (uint32_t*)(smb + OF_PAIR);
        size_t base = (size_t)n0 * FOCUS;
        #pragma unroll 8
        for (int i = 0; i < 64; ++i) {
            int e = i * TPB + tid;
            int idx = is64 ? (int)c64p[base + e] : c32p[base + e];
            unsigned short hb = __half_as_ushort(__float2half_rn(wgt[base + e]));
            pr[e] = ((uint32_t)idx << 16) | (uint32_t)hb;
        }
        uint4 z = make_uint4(0, 0, 0, 0);
        uint4* bz = (uint4*)(smb + OF_B0);
        #pragma unroll
        for (int i = 0; i < 32; ++i) bz[i * TPB + tid] = z;   // B0 + B1
    }

    // ---- A staging (cp.async, 3 stages)
    auto stageA = [&](int kt, int s) {
        uint32_t db = sbase + (uint32_t)s * 32768u;
        #pragma unroll
        for (int it = 0; it < 16; ++it) {
            int c    = it * TPB + tid;               // 0..2047
            int ks   = c >> 8, tl = (c >> 5) & 7, ln = c & 31;
            cp_async16(db + (uint32_t)c * 16,
                       g_xA + ((size_t)(kt * 8 + ks) * 32 + mSlab + tl) * 32 + ln);
        }
    };

    // ---- B scatter: rescan pair table, deposit entries of tile ktn
    auto scatter = [&](int ktn) {
        uint32_t bb = sbase + OF_B0 + (uint32_t)(ktn & 1) * 32768u;
        const uint32_t* pr = (const uint32_t*)(smb + OF_PAIR);
        #pragma unroll 4
        for (int i = 0; i < 64; ++i) {
            int e = i * TPB + tid;
            uint32_t p = pr[e];
            if ((int)(p >> 23) == ktn) {
                int r  = e >> 6;                     // local neuron row
                int k  = (p >> 16) & 1023;
                int ks = (k >> 4) & 7, hi8 = (k >> 3) & 1;
                int t  = (k >> 1) & 3, hl = k & 1;
                int tl = r >> 4, j = (r >> 3) & 1, g = r & 7;
                uint32_t off = (uint32_t)((((ks * 8 + tl) * 32 + g * 4 + t) * 16)
                                          + (j * 2 + hi8) * 4);
                uint32_t val = hl ? ((p & 0xFFFFu) << 16) : (p & 0xFFFFu);
                asm volatile("red.shared.add.noftz.f16x2 [%0], %1;"
                             :: "r"(bb + off), "r"(val) : "memory");
            }
        }
    };
    auto zeroB = [&](int b) {
        uint4 z = make_uint4(0, 0, 0, 0);
        uint4* bz = (uint4*)(smb + OF_B0 + (size_t)b * 32768);
        #pragma unroll
        for (int i = 0; i < 16; ++i) bz[i * TPB + tid] = z;
    };

    stageA(0, 0);
    asm volatile("cp.async.commit_group;" ::: "memory");
    stageA(1, 1);
    asm volatile("cp.async.commit_group;" ::: "memory");
    __syncthreads();                   // pair table + zeros visible
    scatter(0);                        // build B tile kt=0

    float acc[4][4][2][4] = {};        // [m16 i][n16 t][n8 j][c-reg]
    uint4 af[2][4], bf[2][4];

    int slotA = 0;
    for (int kt = 0; kt < KTILES; ++kt) {
        asm volatile("cp.async.wait_group %0;" :: "n"(1) : "memory");
        __syncthreads();               // A[kt] arrived; B[kt&1] scattered

        const char* ta = smb + (size_t)slotA * 32768;
        const char* tb = smb + OF_B0 + (size_t)(kt & 1) * 32768;
        const char* pa = ta + (wm * 4 * 32 + lane) * 16;
        const char* pb = tb + (wn * 4 * 32 + lane) * 16;

        #pragma unroll
        for (int i = 0; i < 4; ++i) {
            af[0][i] = *(const uint4*)(pa + i * 512);
            bf[0][i] = *(const uint4*)(pb + i * 512);
        }

        // first half of the HMMA stream (ks 0..3)
        #pragma unroll
        for (int ks = 0; ks < 4; ++ks) {
            const int cur = ks & 1, nxt = cur ^ 1;
            const char* qa = pa + (ks + 1) * 4096;
            const char* qb = pb + (ks + 1) * 4096;
            #pragma unroll
            for (int i = 0; i < 4; ++i) {
                af[nxt][i] = *(const uint4*)(qa + i * 512);
                bf[nxt][i] = *(const uint4*)(qb + i * 512);
            }
            #pragma unroll
            for (int i = 0; i < 4; ++i)
                #pragma unroll
                for (int t = 0; t < 4; ++t) {
                    mma_f16(acc[i][t][0], af[cur][i], bf[cur][t].x, bf[cur][t].y);
                    mma_f16(acc[i][t][1], af[cur][i], bf[cur][t].z, bf[cur][t].w);
                }
        }

        // hide the next tile's scatter inside the stream
        if (kt + 1 < KTILES) scatter(kt + 1);

        // second half (ks 4..7)
        #pragma unroll
        for (int ks = 4; ks < 8; ++ks) {
            const int cur = ks & 1, nxt = cur ^ 1;
            if (ks < 7) {
                const char* qa = pa + (ks + 1) * 4096;
                const char* qb = pb + (ks + 1) * 4096;
                #pragma unroll
                for (int i = 0; i < 4; ++i) {
                    af[nxt][i] = *(const uint4*)(qa + i * 512);
                    bf[nxt][i] = *(const uint4*)(qb + i * 512);
                }
            }
            #pragma unroll
            for (int i = 0; i < 4; ++i)
                #pragma unroll
                for (int t = 0; t < 4; ++t) {
                    mma_f16(acc[i][t][0], af[cur][i], bf[cur][t].x, bf[cur][t].y);
                    mma_f16(acc[i][t][1], af[cur][i], bf[cur][t].z, bf[cur][t].w);
                }
        }

        if (kt + 2 < KTILES) {
            int ns = slotA + 2; if (ns >= 3) ns -= 3;
            stageA(kt + 2, ns);
        }
        asm volatile("cp.async.commit_group;" ::: "memory");
        __syncthreads();               // scatter(kt+1) complete block-wide
        if (kt + 2 < KTILES) zeroB(kt & 1);   // buffer for tile kt+2
        slotA = slotA == 2 ? 0 : slotA + 1;
    }

    // epilogue: bias add + float2 stores
    const int g = lane >> 2, q = lane & 3;
    const float* sb = (const float*)(smb + OF_BIAS);
    #pragma unroll
    for (int i = 0; i < 4; ++i) {
        #pragma unroll
        for (int hi = 0; hi < 2; ++hi) {
            int row = m0 + (wm * 4 + i) * 16 + hi * 8 + g;
            float* orow = out + (size_t)row * NEURONS + n0;
            #pragma unroll
            for (int t = 0; t < 4; ++t)
                #pragma unroll
                for (int j = 0; j < 2; ++j) {
                    int col = (wn * 4 + t) * 16 + j * 8 + q * 2;
                    float2 v = make_float2(acc[i][t][j][hi * 2 + 0] + sb[col],
                                           acc[i][t][j][hi * 2 + 1] + sb[col + 1]);
                    *(float2*)(orow + col) = v;
                }
        }
    }
}

// ---------------------------------------------------------------------------
extern "C" void kernel_launch(void* const* d_in, const int* in_sizes, int n_in,
                              void* d_out, int out_size) {
    const float* x    = (const float*)d_in[0];
    const void*  conn = d_in[1];                  // int64 (or int32) indices
    const float* wgt  = (const float*)d_in[2];
    const float* bias = (const float*)d_in[3];
    float* out = (float*)d_out;

    cudaFuncSetAttribute(gemm_f16,
                         cudaFuncAttributeMaxDynamicSharedMemorySize, SMEM_DYN);

    convert_x<<<512, 128>>>(x);                   // 1 MB A fragments

    dim3 grid(NEURONS / BN, BATCH / BM);          // 32 x 4 = 128 blocks (1 wave)
    gemm_f16<<<grid, TPB, SMEM_DYN>>>(conn, wgt, bias, out);
}